// round 8
// baseline (speedup 1.0000x reference)
#include <cuda_runtime.h>
#include <cuda_fp16.h>
#include <cstdint>

#define NR 8192
#define MC 8192
#define DD 64

// ---------------- device-global staging (no allocation allowed) ----------------
__device__ __align__(16) __half g_ah[NR * DD];
__device__ __align__(16) __half g_al[NR * DD];
__device__ __align__(16) __half g_bh[MC * DD];
__device__ __align__(16) __half g_bl[MC * DD];
__device__ float2 g_apa[NR];   // a-rows: {|a|^2, 2/(1-|a|^2)}
__device__ float2 g_bq[MC];    // b-rows: {|b|^2, 1/(1-|b|^2)}

// ---------------- helpers ----------------
__device__ __forceinline__ float fast_sqrt(float x) {
    float r; asm("sqrt.approx.f32 %0, %1;" : "=f"(r) : "f"(x)); return r;
}
__device__ __forceinline__ uint32_t smem_u32(const void* p) {
    uint32_t a;
    asm("{ .reg .u64 t; cvta.to.shared.u64 t, %1; cvt.u32.u64 %0, t; }" : "=r"(a) : "l"(p));
    return a;
}
#define CP_ASYNC16(dst, src) \
    asm volatile("cp.async.cg.shared.global [%0], [%1], 16;" :: "r"(dst), "l"(src) : "memory")
#define CP_COMMIT() asm volatile("cp.async.commit_group;" ::: "memory")
#define CP_WAIT0()  asm volatile("cp.async.wait_group 0;" ::: "memory")

#define LDSM4(R, a) \
    asm volatile("ldmatrix.sync.aligned.m8n8.x4.shared.b16 {%0,%1,%2,%3}, [%4];" \
        : "=r"((R)[0]), "=r"((R)[1]), "=r"((R)[2]), "=r"((R)[3]) : "r"(a))

#define MMA16816(d, a, b0, b1) \
    asm volatile("mma.sync.aligned.m16n8k16.row.col.f32.f16.f16.f32 " \
        "{%0,%1,%2,%3}, {%4,%5,%6,%7}, {%8,%9}, {%0,%1,%2,%3};" \
        : "+f"((d)[0]), "+f"((d)[1]), "+f"((d)[2]), "+f"((d)[3]) \
        : "r"((a)[0]), "r"((a)[1]), "r"((a)[2]), "r"((a)[3]), "r"(b0), "r"(b1))

// ---------------- prep: norms + reciprocal terms + fp16 hi/lo split ----------------
__global__ void poincare_prep_kernel(const float* __restrict__ a,
                                     const float* __restrict__ b) {
    int warp = (blockIdx.x * blockDim.x + threadIdx.x) >> 5;
    int lane = threadIdx.x & 31;
    const float* row;
    __half *dh, *dl;
    bool isA = warp < NR;
    int r = isA ? warp : warp - NR;
    if (isA) { row = a + (size_t)r * DD; dh = g_ah + (size_t)r * DD; dl = g_al + (size_t)r * DD; }
    else     { row = b + (size_t)r * DD; dh = g_bh + (size_t)r * DD; dl = g_bl + (size_t)r * DD; }

    float v0 = row[lane], v1 = row[lane + 32];
    __half h0 = __float2half_rn(v0);
    __half l0 = __float2half_rn(v0 - __half2float(h0));
    __half h1 = __float2half_rn(v1);
    __half l1 = __float2half_rn(v1 - __half2float(h1));
    dh[lane] = h0;  dh[lane + 32] = h1;
    dl[lane] = l0;  dl[lane + 32] = l1;

    float s = fmaf(v0, v0, v1 * v1);
    #pragma unroll
    for (int o = 16; o > 0; o >>= 1) s += __shfl_xor_sync(0xffffffffu, s, o);
    if (lane == 0) {
        if (isA) g_apa[r] = make_float2(s, 2.0f / (1.0f - s));
        else     g_bq[r]  = make_float2(s, 1.0f / (1.0f - s));
    }
}

// ---------------- fused Poincare epilogue (previous tile) ----------------
__device__ __forceinline__ void do_epilogue(
    const float acc[2][4][4], int er, const float2 rs[2][2],
    int ec, const float2 cs[4][2], float* __restrict__ out)
{
    #pragma unroll
    for (int mf = 0; mf < 2; mf++) {
        #pragma unroll
        for (int nf = 0; nf < 4; nf++) {
            float res[4];
            #pragma unroll
            for (int q = 0; q < 4; q++) {
                float2 ra = rs[mf][q >> 1];
                float2 cb = cs[nf][q & 1];
                float c  = ra.y * cb.y;
                float sq = fmaf(-2.0f, acc[mf][nf][q], ra.x + cb.x);
                sq = fmaxf(sq, 0.0f);
                float y2 = (sq * c) * c;
                float d  = fast_sqrt(sq);
                float y  = d * c;
                float tt = fmaf(2.0f, y, y2);
                res[q] = __logf(1.0f + y + fast_sqrt(tt));
            }
            size_t r0 = (size_t)(er + mf * 16) * MC + (ec + nf * 8);
            *reinterpret_cast<float2*>(out + r0)          = make_float2(res[0], res[1]);
            *reinterpret_cast<float2*>(out + r0 + 8 * MC) = make_float2(res[2], res[3]);
        }
    }
}

// ---------------- main: persistent + pipelined fp16-split HMMA ----------------
// 256 CTAs = 64 col-bands x 4 row-segments, 32 tiles each. B band resident.
// Cross-tile pipeline: MMA(tile t) issued first, epilogue(tile t-1) runs on
// MUFU/FMA pipes while HMMAs complete. 2 CTAs/SM.
#define PITCH 144
#define BH_BYTES (128 * PITCH)            // 18432
#define A_HALF   (64 * PITCH)             // 9216
#define A_BUF_BYTES (2 * A_HALF)          // 18432
#define OFF_B   0
#define OFF_A   (2 * BH_BYTES)            // 36864
#define SMEM_TOTAL (OFF_A + 2 * A_BUF_BYTES)   // 73728 -> 2 CTAs/SM (smem+regs)

#define SEGS 4
#define BANDS 64
#define TILES_PER 32

__global__ void __launch_bounds__(256, 2)
poincare_hmma_kernel(float* __restrict__ out) {
    extern __shared__ char smem[];
    const uint32_t sb = smem_u32(smem);

    const int tid = threadIdx.x;
    const int lane = tid & 31;
    const int wid = tid >> 5;
    const int wm = wid >> 2;       // 0..1
    const int wn = wid & 3;        // 0..3

    const int band = blockIdx.x & 63;
    const int seg  = blockIdx.x >> 6;        // 0..3
    const int col0 = band * 128;
    const int t0   = seg * TILES_PER;

    // ---- load B band (hi+lo) once + A tile 0 ----
    #pragma unroll
    for (int t = 0; t < 4; t++) {
        int chunk = tid + 256 * t;
        int r = chunk >> 3;
        int kc = chunk & 7;
        uint32_t doff = (uint32_t)(r * PITCH + kc * 16);
        CP_ASYNC16(sb + OFF_B + doff,            g_bh + (size_t)(col0 + r) * DD + kc * 8);
        CP_ASYNC16(sb + OFF_B + BH_BYTES + doff, g_bl + (size_t)(col0 + r) * DD + kc * 8);
    }
    {
        int row0 = t0 * 64;
        #pragma unroll
        for (int t = 0; t < 2; t++) {
            int chunk = tid + 256 * t;
            int r = chunk >> 3;
            int kc = chunk & 7;
            uint32_t doff = (uint32_t)(r * PITCH + kc * 16);
            CP_ASYNC16(sb + OFF_A + doff,          g_ah + (size_t)(row0 + r) * DD + kc * 8);
            CP_ASYNC16(sb + OFF_A + A_HALF + doff, g_al + (size_t)(row0 + r) * DD + kc * 8);
        }
    }
    CP_COMMIT();

    // ---- column stats: fixed for this CTA ----
    const int ec = col0 + wn * 32 + 2 * (lane & 3);
    float2 cs[4][2];
    #pragma unroll
    for (int nf = 0; nf < 4; nf++) {
        cs[nf][0] = __ldg(&g_bq[ec + nf * 8]);
        cs[nf][1] = __ldg(&g_bq[ec + nf * 8 + 1]);
    }

    const uint32_t a_row  = (uint32_t)(wm * 32 + (lane & 15));
    const uint32_t a_koff = (uint32_t)((lane >> 4) * 16);
    const uint32_t b_row  = (uint32_t)(wn * 32 + ((lane & 16) >> 1) + (lane & 7));
    const uint32_t b_koff = (uint32_t)(((lane >> 3) & 1) * 16);
    const uint32_t uBh = sb + OFF_B;
    const uint32_t uBl = sb + OFF_B + BH_BYTES;

    // pipeline state: previous tile's accumulators + stats
    float accP[2][4][4];
    float2 prs[2][2];
    int per = 0;

    for (int it = 0; it < TILES_PER; it++) {
        const int row0 = (t0 + it) * 64;

        CP_WAIT0();
        __syncthreads();

        // ---- prefetch next A tile (other buffer) ----
        if (it + 1 < TILES_PER) {
            int nrow = (t0 + it + 1) * 64;
            uint32_t abase = sb + OFF_A + ((it + 1) & 1) * A_BUF_BYTES;
            #pragma unroll
            for (int t = 0; t < 2; t++) {
                int chunk = tid + 256 * t;
                int r = chunk >> 3;
                int kc = chunk & 7;
                uint32_t doff = (uint32_t)(r * PITCH + kc * 16);
                CP_ASYNC16(abase + doff,          g_ah + (size_t)(nrow + r) * DD + kc * 8);
                CP_ASYNC16(abase + A_HALF + doff, g_al + (size_t)(nrow + r) * DD + kc * 8);
            }
            CP_COMMIT();
        }

        // ---- row stats for current tile ----
        const int er = row0 + wm * 32 + (lane >> 2);
        float2 rs[2][2];
        #pragma unroll
        for (int mf = 0; mf < 2; mf++) {
            rs[mf][0] = __ldg(&g_apa[er + mf * 16]);
            rs[mf][1] = __ldg(&g_apa[er + mf * 16 + 8]);
        }

        // ---- MMA tile `it` into acc (issued first; completes in background) ----
        float acc[2][4][4];
        #pragma unroll
        for (int i = 0; i < 2; i++)
            #pragma unroll
            for (int j = 0; j < 4; j++)
                #pragma unroll
                for (int q = 0; q < 4; q++) acc[i][j][q] = 0.0f;

        const uint32_t uAh = sb + OFF_A + (it & 1) * A_BUF_BYTES;
        const uint32_t uAl = uAh + A_HALF;

        #pragma unroll
        for (int ks = 0; ks < 4; ks++) {
            const uint32_t kb = (uint32_t)(ks * 32);
            uint32_t Ah[2][4], Al[2][4];
            #pragma unroll
            for (int mf = 0; mf < 2; mf++) {
                uint32_t off = (a_row + mf * 16) * PITCH + kb + a_koff;
                LDSM4(Ah[mf], uAh + off);
                LDSM4(Al[mf], uAl + off);
            }
            uint32_t Bh[2][4], Bl[2][4];
            #pragma unroll
            for (int nh = 0; nh < 2; nh++) {
                uint32_t off = (b_row + nh * 16) * PITCH + kb + b_koff;
                LDSM4(Bh[nh], uBh + off);
                LDSM4(Bl[nh], uBl + off);
            }
            #pragma unroll
            for (int nf = 0; nf < 4; nf++) {
                uint32_t bh0 = Bh[nf >> 1][(nf & 1) * 2], bh1 = Bh[nf >> 1][(nf & 1) * 2 + 1];
                uint32_t bl0 = Bl[nf >> 1][(nf & 1) * 2], bl1 = Bl[nf >> 1][(nf & 1) * 2 + 1];
                #pragma unroll
                for (int mf = 0; mf < 2; mf++) {
                    MMA16816(acc[mf][nf], Ah[mf], bh0, bh1);   // hi*hi
                    MMA16816(acc[mf][nf], Ah[mf], bl0, bl1);   // hi*lo
                    MMA16816(acc[mf][nf], Al[mf], bh0, bh1);   // lo*hi
                }
            }
        }

        // ---- epilogue of PREVIOUS tile: overlaps in-flight HMMAs ----
        if (it > 0)
            do_epilogue(accP, per, prs, ec, cs, out);

        // ---- rotate pipeline state (waits on this tile's HMMA completion) ----
        #pragma unroll
        for (int i = 0; i < 2; i++)
            #pragma unroll
            for (int j = 0; j < 4; j++)
                #pragma unroll
                for (int q = 0; q < 4; q++) accP[i][j][q] = acc[i][j][q];
        per = er;
        #pragma unroll
        for (int mf = 0; mf < 2; mf++) {
            prs[mf][0] = rs[mf][0];
            prs[mf][1] = rs[mf][1];
        }
    }

    // ---- drain: epilogue of last tile ----
    do_epilogue(accP, per, prs, ec, cs, out);
}

extern "C" void kernel_launch(void* const* d_in, const int* in_sizes, int n_in,
                              void* d_out, int out_size) {
    const float* a = (const float*)d_in[0];
    const float* b = (const float*)d_in[1];
    float* out = (float*)d_out;

    cudaFuncSetAttribute(poincare_hmma_kernel,
                         cudaFuncAttributeMaxDynamicSharedMemorySize, SMEM_TOTAL);

    poincare_prep_kernel<<<(NR + MC) / 8, 256>>>(a, b);
    poincare_hmma_kernel<<<BANDS * SEGS, 256, SMEM_TOTAL>>>(out);
}